// round 2
// baseline (speedup 1.0000x reference)
#include <cuda_runtime.h>
#include <cuda_bf16.h>
#include <cstdint>

// Problem constants
#define BATCH 2
#define SEQ   2048
#define CDIM  1024
#define NHEAD 16
#define HD    64
#define C3    3072

// ---------------- scratch (device globals; no allocation allowed) -----------
__device__ float g_qkv[BATCH * SEQ * C3];          // 12.6M floats
__device__ float g_q[BATCH * NHEAD * SEQ * HD];    // 4.2M
__device__ float g_k[BATCH * NHEAD * SEQ * HD];
__device__ float g_v[BATCH * NHEAD * SEQ * HD];
__device__ float g_y[BATCH * SEQ * CDIM];          // 4.2M

// ---------------- SGEMM: C = A[MxK] * B[KxN] + bias[N] ----------------------
#define BM 128
#define BN 128
#define BK 8
#define TM 8
#define TN 8

__global__ __launch_bounds__(256, 2) void sgemm_bias_kernel(
    int M, int N, int K,
    const float* __restrict__ A, const float* __restrict__ B,
    const float* __restrict__ bias, float* __restrict__ C)
{
    __shared__ float As[BK][BM];
    __shared__ float Bs[BK][BN];

    const int tid = threadIdx.x;
    const int bx = blockIdx.x;   // N tiles
    const int by = blockIdx.y;   // M tiles

    const int tCol = tid % (BN / TN);   // 0..15
    const int tRow = tid / (BN / TN);   // 0..15

    // A: each thread loads one float4 (128 rows x 8 cols = 256 float4)
    const int aRow = tid >> 1;            // 0..127
    const int aCol = (tid & 1) * 4;       // 0 or 4
    // B: 8 rows x 128 cols = 256 float4
    const int bRow = tid >> 5;            // 0..7
    const int bCol = (tid & 31) * 4;      // 0..124

    const float* Ablk = A + (size_t)by * BM * K;
    const float* Bblk = B + (size_t)bx * BN;

    float acc[TM][TN];
#pragma unroll
    for (int m = 0; m < TM; m++)
#pragma unroll
        for (int n = 0; n < TN; n++) acc[m][n] = 0.f;

    for (int k0 = 0; k0 < K; k0 += BK) {
        float4 a4 = *(const float4*)(Ablk + (size_t)aRow * K + k0 + aCol);
        As[aCol + 0][aRow] = a4.x;
        As[aCol + 1][aRow] = a4.y;
        As[aCol + 2][aRow] = a4.z;
        As[aCol + 3][aRow] = a4.w;
        float4 b4 = *(const float4*)(Bblk + (size_t)(k0 + bRow) * N + bCol);
        *(float4*)&Bs[bRow][bCol] = b4;
        __syncthreads();

        float regM[TM], regN[TN];
#pragma unroll
        for (int k = 0; k < BK; k++) {
#pragma unroll
            for (int m = 0; m < TM; m++) regM[m] = As[k][tRow * TM + m];
#pragma unroll
            for (int n = 0; n < TN; n++) regN[n] = Bs[k][tCol * TN + n];
#pragma unroll
            for (int m = 0; m < TM; m++)
#pragma unroll
                for (int n = 0; n < TN; n++) acc[m][n] += regM[m] * regN[n];
        }
        __syncthreads();
    }

    // epilogue with bias
#pragma unroll
    for (int m = 0; m < TM; m++) {
        const int row = by * BM + tRow * TM + m;
        float* Crow = C + (size_t)row * N + bx * BN + tCol * TN;
        const float* brow = bias + bx * BN + tCol * TN;
#pragma unroll
        for (int n = 0; n < TN; n += 4) {
            float4 o;
            o.x = acc[m][n + 0] + brow[n + 0];
            o.y = acc[m][n + 1] + brow[n + 1];
            o.z = acc[m][n + 2] + brow[n + 2];
            o.w = acc[m][n + 3] + brow[n + 3];
            *(float4*)(Crow + n) = o;
        }
    }
}

// ---------------- RoPE (head-indexed angle!) + scatter to [B,H,T,hd] --------
__global__ __launch_bounds__(256) void rope_scatter_kernel(
    const float* __restrict__ qkv,
    float* __restrict__ q, float* __restrict__ k, float* __restrict__ v)
{
    int idx = blockIdx.x * blockDim.x + threadIdx.x;   // [B][T][H][HD/2]
    const int total = BATCH * SEQ * NHEAD * (HD / 2);
    if (idx >= total) return;

    const int d2 = idx & 31;
    const int h  = (idx >> 5) & 15;
    const int t  = (idx >> 9) & (SEQ - 1);
    const int b  = idx >> 20;  // 32*16*2048 = 2^20

    const float* row = qkv + ((size_t)(b * SEQ + t)) * C3;

    // theta = 10000^(-2*d2/64); angle = head_index * theta (source quirk)
    const float theta = __powf(10000.0f, -(2.0f * d2) / 64.0f);
    float s, c;
    sincosf((float)h * theta, &s, &c);

    const size_t o = (((size_t)(b * NHEAD + h)) * SEQ + t) * HD + 2 * d2;
    const int qc = h * HD + 2 * d2;

    float q0 = row[qc], q1 = row[qc + 1];
    q[o]     = q0 * c - q1 * s;
    q[o + 1] = q1 * c + q0 * s;

    float k0 = row[CDIM + qc], k1 = row[CDIM + qc + 1];
    k[o]     = k0 * c - k1 * s;
    k[o + 1] = k1 * c + k0 * s;

    v[o]     = row[2 * CDIM + qc];
    v[o + 1] = row[2 * CDIM + qc + 1];
}

// ---------------- Flash attention (causal), 64x64 tiles ---------------------
#define AQ 64
#define AK 64
#define APAD 4
#define ASTR (HD + APAD)   // 68

__global__ __launch_bounds__(256) void attn_kernel(
    const float* __restrict__ Qg, const float* __restrict__ Kg,
    const float* __restrict__ Vg, float* __restrict__ Y)
{
    extern __shared__ float sm[];
    float* Qs   = sm;                     // [64][68]
    float* KS   = Qs + AQ * ASTR;         // K tile, reused for S/P
    float* Vs   = KS + AK * ASTR;         // [64][68]
    float* mrow = Vs + AK * ASTR;         // [64]
    float* lrow = mrow + AQ;              // [64]
    float* arow = lrow + AQ;              // [64]

    const int tid = threadIdx.x;
    const int qt  = blockIdx.x;           // q tile (0..31)
    const int h   = blockIdx.y;
    const int b   = blockIdx.z;

    const size_t headOff = ((size_t)(b * NHEAD + h)) * SEQ * HD;
    const float* Qh = Qg + headOff;
    const float* Kh = Kg + headOff;
    const float* Vh = Vg + headOff;

    // load Q tile
    for (int i = tid; i < AQ * HD / 4; i += 256) {
        int r = i / (HD / 4), c4 = i % (HD / 4);
        *(float4*)&Qs[r * ASTR + c4 * 4] =
            *(const float4*)(Qh + (size_t)(qt * AQ + r) * HD + c4 * 4);
    }
    if (tid < AQ) { mrow[tid] = -1e30f; lrow[tid] = 0.0f; }

    const int tCol = tid & 15;   // 16x16 thread grid, 4x4 tiles
    const int tRow = tid >> 4;

    float Oacc[4][4];
#pragma unroll
    for (int m = 0; m < 4; m++)
#pragma unroll
        for (int n = 0; n < 4; n++) Oacc[m][n] = 0.f;

    for (int kt = 0; kt <= qt; kt++) {
        __syncthreads();   // protects KS/Vs reuse + first-iter Qs/m/l visibility
        for (int i = tid; i < AK * HD / 4; i += 256) {
            int r = i / (HD / 4), c4 = i % (HD / 4);
            *(float4*)&KS[r * ASTR + c4 * 4] =
                *(const float4*)(Kh + (size_t)(kt * AK + r) * HD + c4 * 4);
            *(float4*)&Vs[r * ASTR + c4 * 4] =
                *(const float4*)(Vh + (size_t)(kt * AK + r) * HD + c4 * 4);
        }
        __syncthreads();

        // S = Q K^T
        float s[4][4];
#pragma unroll
        for (int m = 0; m < 4; m++)
#pragma unroll
            for (int n = 0; n < 4; n++) s[m][n] = 0.f;
#pragma unroll
        for (int d = 0; d < HD; d++) {
            float qv[4], kv[4];
#pragma unroll
            for (int m = 0; m < 4; m++) qv[m] = Qs[(tRow * 4 + m) * ASTR + d];
#pragma unroll
            for (int n = 0; n < 4; n++) kv[n] = KS[(tCol * 4 + n) * ASTR + d];
#pragma unroll
            for (int m = 0; m < 4; m++)
#pragma unroll
                for (int n = 0; n < 4; n++) s[m][n] += qv[m] * kv[n];
        }
        __syncthreads();   // everyone done reading K

        // scale + causal mask, write S into KS buffer
        const bool diag = (kt == qt);
#pragma unroll
        for (int m = 0; m < 4; m++) {
            int qi = tRow * 4 + m;
#pragma unroll
            for (int n = 0; n < 4; n++) {
                int kj = tCol * 4 + n;
                float val = s[m][n] * 0.125f;   // 1/sqrt(64)
                if (diag && kj > qi) val = -1e30f;
                KS[qi * ASTR + kj] = val;
            }
        }
        __syncthreads();

        // online softmax: 4 threads per row
        {
            const int row = tid >> 2;
            const int l4  = tid & 3;
            float* Sr = &KS[row * ASTR + l4 * 16];
            float mx = -1e30f;
#pragma unroll
            for (int j = 0; j < 16; j++) mx = fmaxf(mx, Sr[j]);
            mx = fmaxf(mx, __shfl_xor_sync(0xffffffffu, mx, 1));
            mx = fmaxf(mx, __shfl_xor_sync(0xffffffffu, mx, 2));
            const float mold = mrow[row];
            const float mnew = fmaxf(mold, mx);
            float sum = 0.f;
#pragma unroll
            for (int j = 0; j < 16; j++) {
                float p = __expf(Sr[j] - mnew);
                Sr[j] = p;
                sum += p;
            }
            sum += __shfl_xor_sync(0xffffffffu, sum, 1);
            sum += __shfl_xor_sync(0xffffffffu, sum, 2);
            if (l4 == 0) {
                float alpha = __expf(mold - mnew);
                mrow[row] = mnew;
                lrow[row] = lrow[row] * alpha + sum;
                arow[row] = alpha;
            }
        }
        __syncthreads();

        // rescale O, then O += P @ V
#pragma unroll
        for (int m = 0; m < 4; m++) {
            float al = arow[tRow * 4 + m];
#pragma unroll
            for (int n = 0; n < 4; n++) Oacc[m][n] *= al;
        }
#pragma unroll
        for (int j = 0; j < AK; j++) {
            float pv[4], vv[4];
#pragma unroll
            for (int m = 0; m < 4; m++) pv[m] = KS[(tRow * 4 + m) * ASTR + j];
#pragma unroll
            for (int n = 0; n < 4; n++) vv[n] = Vs[j * ASTR + tCol * 4 + n];
#pragma unroll
            for (int m = 0; m < 4; m++)
#pragma unroll
                for (int n = 0; n < 4; n++) Oacc[m][n] += pv[m] * vv[n];
        }
    }
    __syncthreads();

    // normalize & write to Y[B,T,C] at column h*64 + d
#pragma unroll
    for (int m = 0; m < 4; m++) {
        const int qi = tRow * 4 + m;
        const float inv = 1.0f / lrow[qi];
        const int t = qt * AQ + qi;
        float* yp = Y + ((size_t)b * SEQ + t) * CDIM + h * HD + tCol * 4;
        float4 o;
        o.x = Oacc[m][0] * inv;
        o.y = Oacc[m][1] * inv;
        o.z = Oacc[m][2] * inv;
        o.w = Oacc[m][3] * inv;
        *(float4*)yp = o;
    }
}

// ---------------- launch ----------------------------------------------------
extern "C" void kernel_launch(void* const* d_in, const int* in_sizes, int n_in,
                              void* d_out, int out_size)
{
    const float* x      = (const float*)d_in[0];
    const float* W_attn = (const float*)d_in[1];
    const float* b_attn = (const float*)d_in[2];
    const float* W_proj = (const float*)d_in[3];
    const float* b_proj = (const float*)d_in[4];
    float* out = (float*)d_out;

    float *qkv, *q, *k, *v, *y;
    cudaGetSymbolAddress((void**)&qkv, g_qkv);
    cudaGetSymbolAddress((void**)&q,   g_q);
    cudaGetSymbolAddress((void**)&k,   g_k);
    cudaGetSymbolAddress((void**)&v,   g_v);
    cudaGetSymbolAddress((void**)&y,   g_y);

    const int M = BATCH * SEQ;   // 4096

    // GEMM1: qkv = x @ W_attn + b_attn
    {
        dim3 grid(C3 / BN, M / BM);
        sgemm_bias_kernel<<<grid, 256>>>(M, C3, CDIM, x, W_attn, b_attn, qkv);
    }
    // RoPE + scatter
    {
        int total = BATCH * SEQ * NHEAD * (HD / 2);
        rope_scatter_kernel<<<(total + 255) / 256, 256>>>(qkv, q, k, v);
    }
    // Flash attention
    {
        const int smem = (3 * AQ * ASTR + 3 * AQ) * sizeof(float);  // ~53KB
        cudaFuncSetAttribute(attn_kernel,
                             cudaFuncAttributeMaxDynamicSharedMemorySize, smem);
        dim3 grid(SEQ / AQ, NHEAD, BATCH);
        attn_kernel<<<grid, 256, smem>>>(q, k, v, y);
    }
    // GEMM2: out = y @ W_proj + b_proj
    {
        dim3 grid(CDIM / BN, M / BM);
        sgemm_bias_kernel<<<grid, 256>>>(M, CDIM, CDIM, y, W_proj, b_proj, out);
    }
}

// round 7
// speedup vs baseline: 1.3032x; 1.3032x over previous
#include <cuda_runtime.h>
#include <cuda_bf16.h>
#include <cstdint>

// Problem constants
#define BATCH 2
#define SEQ   2048
#define CDIM  1024
#define NHEAD 16
#define HD    64
#define C3    3072
#define MROWS (BATCH * SEQ)   // 4096

// ---------------- scratch (device globals; no allocation allowed) -----------
__device__ float g_qkv[BATCH * SEQ * C3];
__device__ float g_q[BATCH * NHEAD * SEQ * HD];
__device__ float g_k[BATCH * NHEAD * SEQ * HD];
__device__ float g_v[BATCH * NHEAD * SEQ * HD];
__device__ float g_y[BATCH * SEQ * CDIM];

// bf16 split-precision operand scratch
__device__ __nv_bfloat16 g_ahi[MROWS * CDIM];       // activations hi (x, then y)
__device__ __nv_bfloat16 g_alo[MROWS * CDIM];       // activations lo
__device__ __nv_bfloat16 g_w1hi[C3 * CDIM];         // W_attn^T hi  [N=3072, K=1024]
__device__ __nv_bfloat16 g_w1lo[C3 * CDIM];
__device__ __nv_bfloat16 g_w2hi[CDIM * CDIM];       // W_proj^T hi  [N=1024, K=1024]
__device__ __nv_bfloat16 g_w2lo[CDIM * CDIM];

// ================= PTX helpers (plain sm_80+ PTX only) =======================
__device__ __forceinline__ uint32_t smem_u32(const void* p) {
    uint32_t a;
    asm("{ .reg .u64 tmp; cvta.to.shared.u64 tmp, %1; cvt.u32.u64 %0, tmp; }"
        : "=r"(a) : "l"(p));
    return a;
}
__device__ __forceinline__ void cp16(uint32_t s, const void* g) {
    asm volatile("cp.async.cg.shared.global [%0], [%1], 16;" :: "r"(s), "l"(g));
}
#define CP_COMMIT()  asm volatile("cp.async.commit_group;" ::: "memory")
#define CP_WAIT_1()  asm volatile("cp.async.wait_group 1;" ::: "memory")
#define CP_WAIT_0()  asm volatile("cp.async.wait_group 0;" ::: "memory")

#define LDM_X4(r, addr) \
    asm volatile("ldmatrix.sync.aligned.m8n8.x4.shared.b16 {%0,%1,%2,%3}, [%4];" \
                 : "=r"((r)[0]), "=r"((r)[1]), "=r"((r)[2]), "=r"((r)[3]) : "r"(addr))

#define MMA16816(c, a, b0, b1) \
    asm volatile("mma.sync.aligned.m16n8k16.row.col.f32.bf16.bf16.f32 " \
                 "{%0,%1,%2,%3}, {%4,%5,%6,%7}, {%8,%9}, {%0,%1,%2,%3};" \
                 : "+f"((c)[0]), "+f"((c)[1]), "+f"((c)[2]), "+f"((c)[3]) \
                 : "r"((a)[0]), "r"((a)[1]), "r"((a)[2]), "r"((a)[3]), \
                   "r"(b0), "r"(b1))

// ================= operand conversion kernels ================================
__global__ __launch_bounds__(256) void convert_split_kernel(
    int total4, const float4* __restrict__ src,
    __nv_bfloat162* __restrict__ hi, __nv_bfloat162* __restrict__ lo)
{
    int i = blockIdx.x * blockDim.x + threadIdx.x;
    if (i >= total4) return;
    float4 v = src[i];
    __nv_bfloat16 hx = __float2bfloat16(v.x), hy = __float2bfloat16(v.y);
    __nv_bfloat16 hz = __float2bfloat16(v.z), hw = __float2bfloat16(v.w);
    hi[2 * i]     = __nv_bfloat162(hx, hy);
    hi[2 * i + 1] = __nv_bfloat162(hz, hw);
    lo[2 * i]     = __nv_bfloat162(__float2bfloat16(v.x - __bfloat162float(hx)),
                                   __float2bfloat16(v.y - __bfloat162float(hy)));
    lo[2 * i + 1] = __nv_bfloat162(__float2bfloat16(v.z - __bfloat162float(hz)),
                                   __float2bfloat16(v.w - __bfloat162float(hw)));
}

__global__ __launch_bounds__(256) void transpose_split_kernel(
    int K, int N, const float* __restrict__ W,
    __nv_bfloat16* __restrict__ Thi, __nv_bfloat16* __restrict__ Tlo)
{
    __shared__ float t[32][33];
    const int n0 = blockIdx.x * 32, k0 = blockIdx.y * 32;
    const int tx = threadIdx.x, ty = threadIdx.y;   // 32 x 8
#pragma unroll
    for (int j = 0; j < 4; j++) {
        int k = k0 + ty + j * 8;
        t[ty + j * 8][tx] = W[(size_t)k * N + n0 + tx];
    }
    __syncthreads();
#pragma unroll
    for (int j = 0; j < 4; j++) {
        int n = n0 + ty + j * 8;
        int k = k0 + tx;
        float v = t[tx][ty + j * 8];
        __nv_bfloat16 h = __float2bfloat16(v);
        Thi[(size_t)n * K + k] = h;
        Tlo[(size_t)n * K + k] = __float2bfloat16(v - __bfloat162float(h));
    }
}

// ================= mma.sync GEMM: C[M,N] = A[M,K] @ Bt[N,K]^T + bias =========
// Split precision: acc += Ahi*Bhi + Ahi*Blo + Alo*Bhi.
// 128x128 tile, BK=32, 8 warps (4x2), warp tile 32x64, 2-stage cp.async.
#define GBK   32
#define PSTR  40                       // padded row stride in bf16 (80 bytes)
#define PART_SM  (128 * PSTR * 2)      // 10240 B per operand part
#define STAGE_SM (4 * PART_SM)         // 40960 B
#define GEMM_SMEM (2 * STAGE_SM)       // 81920 B

__global__ __launch_bounds__(256) void gemm_mma_kernel(
    int K, int N,
    const __nv_bfloat16* __restrict__ Ahi, const __nv_bfloat16* __restrict__ Alo,
    const __nv_bfloat16* __restrict__ Bhi, const __nv_bfloat16* __restrict__ Blo,
    const float* __restrict__ bias, float* __restrict__ C)
{
    extern __shared__ char smem[];
    const uint32_t smb = smem_u32(smem);
    const int tid = threadIdx.x;
    const int lane = tid & 31;
    const int wid = tid >> 5;
    const int bx = blockIdx.x;   // N tile
    const int by = blockIdx.y;   // M tile
    const int wm = wid >> 1;     // 0..3
    const int wn = wid & 1;      // 0..1

    const __nv_bfloat16* src[4];
    src[0] = Ahi + (size_t)by * 128 * K;
    src[1] = Alo + (size_t)by * 128 * K;
    src[2] = Bhi + (size_t)bx * 128 * K;
    src[3] = Blo + (size_t)bx * 128 * K;

    const int lr = tid >> 1;          // row 0..127 for loading
    const int lu = (tid & 1) * 2;     // 16B-unit 0 or 2

    float acc[2][8][4];
#pragma unroll
    for (int mt = 0; mt < 2; mt++)
#pragma unroll
        for (int nt = 0; nt < 8; nt++)
#pragma unroll
            for (int j = 0; j < 4; j++) acc[mt][nt][j] = 0.f;

    const int nch = K / GBK;

    // prologue: issue chunk 0 into stage 0
    {
        const uint32_t sb = smb;
#pragma unroll
        for (int p = 0; p < 4; p++) {
            const char* g = (const char*)(src[p] + (size_t)lr * K);
            uint32_t s = sb + p * PART_SM + lr * 80 + lu * 16;
            cp16(s,      g + lu * 16);
            cp16(s + 16, g + lu * 16 + 16);
        }
        CP_COMMIT();
    }

    for (int ch = 0; ch < nch; ch++) {
        if (ch + 1 < nch) {
            const uint32_t sb = smb + ((ch + 1) & 1) * STAGE_SM;
            const int koff = (ch + 1) * GBK;
#pragma unroll
            for (int p = 0; p < 4; p++) {
                const char* g = (const char*)(src[p] + (size_t)lr * K + koff);
                uint32_t s = sb + p * PART_SM + lr * 80 + lu * 16;
                cp16(s,      g + lu * 16);
                cp16(s + 16, g + lu * 16 + 16);
            }
            CP_COMMIT();
            CP_WAIT_1();
        } else {
            CP_WAIT_0();
        }
        __syncthreads();

        // compute on stage ch&1
        const uint32_t sb = smb + (ch & 1) * STAGE_SM;
#pragma unroll
        for (int ks = 0; ks < 2; ks++) {
            const int kb = ks * 16;
            // A fragments: [part][mtile][4]
            uint32_t a[2][2][4];
#pragma unroll
            for (int pp = 0; pp < 2; pp++) {
#pragma unroll
                for (int mt = 0; mt < 2; mt++) {
                    int row = wm * 32 + mt * 16 + (lane & 7) + ((lane >> 3) & 1) * 8;
                    int kk  = kb + ((lane >> 4) & 1) * 8;
                    uint32_t ad = sb + pp * PART_SM + row * 80 + kk * 2;
                    LDM_X4(a[pp][mt], ad);
                }
            }
#pragma unroll
            for (int np = 0; np < 4; np++) {
                int rowb = wn * 64 + np * 16 + (lane & 7) + ((lane >> 4) & 1) * 8;
                int kk   = kb + ((lane >> 3) & 1) * 8;
                uint32_t bh[4], bl[4];
                LDM_X4(bh, sb + 2 * PART_SM + rowb * 80 + kk * 2);
                LDM_X4(bl, sb + 3 * PART_SM + rowb * 80 + kk * 2);
#pragma unroll
                for (int half = 0; half < 2; half++) {
                    const int nt = np * 2 + half;
                    const uint32_t b0h = bh[half * 2], b1h = bh[half * 2 + 1];
                    const uint32_t b0l = bl[half * 2], b1l = bl[half * 2 + 1];
#pragma unroll
                    for (int mt = 0; mt < 2; mt++) {
                        MMA16816(acc[mt][nt], a[0][mt], b0h, b1h);   // hi*hi
                        MMA16816(acc[mt][nt], a[0][mt], b0l, b1l);   // hi*lo
                        MMA16816(acc[mt][nt], a[1][mt], b0h, b1h);   // lo*hi
                    }
                }
            }
        }
        __syncthreads();
    }

    // epilogue: c-frag thread mapping: g = lane>>2, cn = (lane&3)*2
    const int g  = lane >> 2;
    const int cn = (lane & 3) * 2;
#pragma unroll
    for (int mt = 0; mt < 2; mt++) {
        const int row = by * 128 + wm * 32 + mt * 16 + g;
#pragma unroll
        for (int nt = 0; nt < 8; nt++) {
            const int col = bx * 128 + wn * 64 + nt * 8 + cn;
            const float2 bb = *(const float2*)(bias + col);
            float2 o0, o1;
            o0.x = acc[mt][nt][0] + bb.x;
            o0.y = acc[mt][nt][1] + bb.y;
            o1.x = acc[mt][nt][2] + bb.x;
            o1.y = acc[mt][nt][3] + bb.y;
            *(float2*)(C + (size_t)row * N + col)       = o0;
            *(float2*)(C + (size_t)(row + 8) * N + col) = o1;
        }
    }
}

// ---------------- RoPE (head-indexed angle!) + scatter to [B,H,T,hd] --------
__global__ __launch_bounds__(256) void rope_scatter_kernel(
    const float* __restrict__ qkv,
    float* __restrict__ q, float* __restrict__ k, float* __restrict__ v)
{
    int idx = blockIdx.x * blockDim.x + threadIdx.x;
    const int total = BATCH * SEQ * NHEAD * (HD / 2);
    if (idx >= total) return;

    const int d2 = idx & 31;
    const int h  = (idx >> 5) & 15;
    const int t  = (idx >> 9) & (SEQ - 1);
    const int b  = idx >> 20;

    const float* row = qkv + ((size_t)(b * SEQ + t)) * C3;
    const float theta = __powf(10000.0f, -(2.0f * d2) / 64.0f);
    float s, c;
    sincosf((float)h * theta, &s, &c);

    const size_t o = (((size_t)(b * NHEAD + h)) * SEQ + t) * HD + 2 * d2;
    const int qc = h * HD + 2 * d2;

    float q0 = row[qc], q1 = row[qc + 1];
    q[o]     = q0 * c - q1 * s;
    q[o + 1] = q1 * c + q0 * s;

    float k0 = row[CDIM + qc], k1 = row[CDIM + qc + 1];
    k[o]     = k0 * c - k1 * s;
    k[o + 1] = k1 * c + k0 * s;

    v[o]     = row[2 * CDIM + qc];
    v[o + 1] = row[2 * CDIM + qc + 1];
}

// ---------------- Flash attention (causal), 64x64 tiles (fp32) --------------
#define AQ 64
#define AK 64
#define APAD 4
#define ASTR (HD + APAD)   // 68

__global__ __launch_bounds__(256) void attn_kernel(
    const float* __restrict__ Qg, const float* __restrict__ Kg,
    const float* __restrict__ Vg, float* __restrict__ Y)
{
    extern __shared__ float sm[];
    float* Qs   = sm;
    float* KS   = Qs + AQ * ASTR;
    float* Vs   = KS + AK * ASTR;
    float* mrow = Vs + AK * ASTR;
    float* lrow = mrow + AQ;
    float* arow = lrow + AQ;

    const int tid = threadIdx.x;
    const int qt  = blockIdx.x;
    const int h   = blockIdx.y;
    const int b   = blockIdx.z;

    const size_t headOff = ((size_t)(b * NHEAD + h)) * SEQ * HD;
    const float* Qh = Qg + headOff;
    const float* Kh = Kg + headOff;
    const float* Vh = Vg + headOff;

    for (int i = tid; i < AQ * HD / 4; i += 256) {
        int r = i / (HD / 4), c4 = i % (HD / 4);
        *(float4*)&Qs[r * ASTR + c4 * 4] =
            *(const float4*)(Qh + (size_t)(qt * AQ + r) * HD + c4 * 4);
    }
    if (tid < AQ) { mrow[tid] = -1e30f; lrow[tid] = 0.0f; }

    const int tCol = tid & 15;
    const int tRow = tid >> 4;

    float Oacc[4][4];
#pragma unroll
    for (int m = 0; m < 4; m++)
#pragma unroll
        for (int n = 0; n < 4; n++) Oacc[m][n] = 0.f;

    for (int kt = 0; kt <= qt; kt++) {
        __syncthreads();
        for (int i = tid; i < AK * HD / 4; i += 256) {
            int r = i / (HD / 4), c4 = i % (HD / 4);
            *(float4*)&KS[r * ASTR + c4 * 4] =
                *(const float4*)(Kh + (size_t)(kt * AK + r) * HD + c4 * 4);
            *(float4*)&Vs[r * ASTR + c4 * 4] =
                *(const float4*)(Vh + (size_t)(kt * AK + r) * HD + c4 * 4);
        }
        __syncthreads();

        float s[4][4];
#pragma unroll
        for (int m = 0; m < 4; m++)
#pragma unroll
            for (int n = 0; n < 4; n++) s[m][n] = 0.f;
#pragma unroll
        for (int d = 0; d < HD; d++) {
            float qv[4], kv[4];
#pragma unroll
            for (int m = 0; m < 4; m++) qv[m] = Qs[(tRow * 4 + m) * ASTR + d];
#pragma unroll
            for (int n = 0; n < 4; n++) kv[n] = KS[(tCol * 4 + n) * ASTR + d];
#pragma unroll
            for (int m = 0; m < 4; m++)
#pragma unroll
                for (int n = 0; n < 4; n++) s[m][n] += qv[m] * kv[n];
        }
        __syncthreads();

        const bool diag = (kt == qt);
#pragma unroll
        for (int m = 0; m < 4; m++) {
            int qi = tRow * 4 + m;
#pragma unroll
            for (int n = 0; n < 4; n++) {
                int kj = tCol * 4 + n;
                float val = s[m][n] * 0.125f;
                if (diag && kj > qi) val = -1e30f;
                KS[qi * ASTR + kj] = val;
            }
        }
        __syncthreads();

        {
            const int row = tid >> 2;
            const int l4  = tid & 3;
            float* Sr = &KS[row * ASTR + l4 * 16];
            float mx = -1e30f;
#pragma unroll
            for (int j = 0; j < 16; j++) mx = fmaxf(mx, Sr[j]);
            mx = fmaxf(mx, __shfl_xor_sync(0xffffffffu, mx, 1));
            mx = fmaxf(mx, __shfl_xor_sync(0xffffffffu, mx, 2));
            const float mold = mrow[row];
            const float mnew = fmaxf(mold, mx);
            float sum = 0.f;
#pragma unroll
            for (int j = 0; j < 16; j++) {
                float p = __expf(Sr[j] - mnew);
                Sr[j] = p;
                sum += p;
            }
            sum += __shfl_xor_sync(0xffffffffu, sum, 1);
            sum += __shfl_xor_sync(0xffffffffu, sum, 2);
            if (l4 == 0) {
                float alpha = __expf(mold - mnew);
                mrow[row] = mnew;
                lrow[row] = lrow[row] * alpha + sum;
                arow[row] = alpha;
            }
        }
        __syncthreads();

#pragma unroll
        for (int m = 0; m < 4; m++) {
            float al = arow[tRow * 4 + m];
#pragma unroll
            for (int n = 0; n < 4; n++) Oacc[m][n] *= al;
        }
#pragma unroll
        for (int j = 0; j < AK; j++) {
            float pv[4], vv[4];
#pragma unroll
            for (int m = 0; m < 4; m++) pv[m] = KS[(tRow * 4 + m) * ASTR + j];
#pragma unroll
            for (int n = 0; n < 4; n++) vv[n] = Vs[j * ASTR + tCol * 4 + n];
#pragma unroll
            for (int m = 0; m < 4; m++)
#pragma unroll
                for (int n = 0; n < 4; n++) Oacc[m][n] += pv[m] * vv[n];
        }
    }
    __syncthreads();

#pragma unroll
    for (int m = 0; m < 4; m++) {
        const int qi = tRow * 4 + m;
        const float inv = 1.0f / lrow[qi];
        const int t = qt * AQ + qi;
        float* yp = Y + ((size_t)b * SEQ + t) * CDIM + h * HD + tCol * 4;
        float4 o;
        o.x = Oacc[m][0] * inv;
        o.y = Oacc[m][1] * inv;
        o.z = Oacc[m][2] * inv;
        o.w = Oacc[m][3] * inv;
        *(float4*)yp = o;
    }
}

// ---------------- launch ----------------------------------------------------
extern "C" void kernel_launch(void* const* d_in, const int* in_sizes, int n_in,
                              void* d_out, int out_size)
{
    const float* x      = (const float*)d_in[0];
    const float* W_attn = (const float*)d_in[1];
    const float* b_attn = (const float*)d_in[2];
    const float* W_proj = (const float*)d_in[3];
    const float* b_proj = (const float*)d_in[4];
    float* out = (float*)d_out;

    float *qkv, *q, *k, *v, *y;
    __nv_bfloat16 *ahi, *alo, *w1hi, *w1lo, *w2hi, *w2lo;
    cudaGetSymbolAddress((void**)&qkv,  g_qkv);
    cudaGetSymbolAddress((void**)&q,    g_q);
    cudaGetSymbolAddress((void**)&k,    g_k);
    cudaGetSymbolAddress((void**)&v,    g_v);
    cudaGetSymbolAddress((void**)&y,    g_y);
    cudaGetSymbolAddress((void**)&ahi,  g_ahi);
    cudaGetSymbolAddress((void**)&alo,  g_alo);
    cudaGetSymbolAddress((void**)&w1hi, g_w1hi);
    cudaGetSymbolAddress((void**)&w1lo, g_w1lo);
    cudaGetSymbolAddress((void**)&w2hi, g_w2hi);
    cudaGetSymbolAddress((void**)&w2lo, g_w2lo);

    cudaFuncSetAttribute(gemm_mma_kernel,
                         cudaFuncAttributeMaxDynamicSharedMemorySize, GEMM_SMEM);

    // convert weights (transpose + split)
    {
        dim3 blk(32, 8);
        dim3 g1(C3 / 32, CDIM / 32);
        transpose_split_kernel<<<g1, blk>>>(CDIM, C3, W_attn, w1hi, w1lo);
        dim3 g2(CDIM / 32, CDIM / 32);
        transpose_split_kernel<<<g2, blk>>>(CDIM, CDIM, W_proj, w2hi, w2lo);
    }
    // convert x
    {
        int total4 = MROWS * CDIM / 4;
        convert_split_kernel<<<(total4 + 255) / 256, 256>>>(
            total4, (const float4*)x, (__nv_bfloat162*)ahi, (__nv_bfloat162*)alo);
    }
    // GEMM1: qkv = x @ W_attn + b_attn
    {
        dim3 grid(C3 / 128, MROWS / 128);
        gemm_mma_kernel<<<grid, 256, GEMM_SMEM>>>(CDIM, C3,
                                                  ahi, alo, w1hi, w1lo, b_attn, qkv);
    }
    // RoPE + scatter
    {
        int total = BATCH * SEQ * NHEAD * (HD / 2);
        rope_scatter_kernel<<<(total + 255) / 256, 256>>>(qkv, q, k, v);
    }
    // Flash attention (fp32)
    {
        const int smem = (3 * AQ * ASTR + 3 * AQ) * sizeof(float);
        cudaFuncSetAttribute(attn_kernel,
                             cudaFuncAttributeMaxDynamicSharedMemorySize, smem);
        dim3 grid(SEQ / AQ, NHEAD, BATCH);
        attn_kernel<<<grid, 256, smem>>>(q, k, v, y);
    }
    // convert y
    {
        int total4 = MROWS * CDIM / 4;
        convert_split_kernel<<<(total4 + 255) / 256, 256>>>(
            total4, (const float4*)y, (__nv_bfloat162*)ahi, (__nv_bfloat162*)alo);
    }
    // GEMM2: out = y @ W_proj + b_proj
    {
        dim3 grid(CDIM / 128, MROWS / 128);
        gemm_mma_kernel<<<grid, 256, GEMM_SMEM>>>(CDIM, CDIM,
                                                  ahi, alo, w2hi, w2lo, b_proj, out);
    }
}

// round 10
// speedup vs baseline: 2.6272x; 2.0159x over previous
#include <cuda_runtime.h>
#include <cuda_bf16.h>
#include <cstdint>

// Problem constants
#define BATCH 2
#define SEQ   2048
#define CDIM  1024
#define NHEAD 16
#define HD    64
#define C3    3072
#define MROWS (BATCH * SEQ)   // 4096

// ---------------- scratch (device globals; no allocation allowed) -----------
__device__ float g_qkv[BATCH * SEQ * C3];
__device__ float g_y[BATCH * SEQ * CDIM];

// bf16 split-precision operand scratch
__device__ __nv_bfloat16 g_ahi[MROWS * CDIM];
__device__ __nv_bfloat16 g_alo[MROWS * CDIM];
__device__ __nv_bfloat16 g_w1hi[C3 * CDIM];
__device__ __nv_bfloat16 g_w1lo[C3 * CDIM];
__device__ __nv_bfloat16 g_w2hi[CDIM * CDIM];
__device__ __nv_bfloat16 g_w2lo[CDIM * CDIM];

// attention operands, [B,H,T,hd] bf16 hi/lo
#define QKV_ELEMS (BATCH * NHEAD * SEQ * HD)
__device__ __nv_bfloat16 g_qhi[QKV_ELEMS];
__device__ __nv_bfloat16 g_qlo[QKV_ELEMS];
__device__ __nv_bfloat16 g_khi[QKV_ELEMS];
__device__ __nv_bfloat16 g_klo[QKV_ELEMS];
__device__ __nv_bfloat16 g_vhi[QKV_ELEMS];
__device__ __nv_bfloat16 g_vlo[QKV_ELEMS];

// ================= PTX helpers (plain sm_80+ PTX only) =======================
__device__ __forceinline__ uint32_t smem_u32(const void* p) {
    uint32_t a;
    asm("{ .reg .u64 tmp; cvta.to.shared.u64 tmp, %1; cvt.u32.u64 %0, tmp; }"
        : "=r"(a) : "l"(p));
    return a;
}
__device__ __forceinline__ void cp16(uint32_t s, const void* g) {
    asm volatile("cp.async.cg.shared.global [%0], [%1], 16;" :: "r"(s), "l"(g));
}
#define CP_COMMIT()  asm volatile("cp.async.commit_group;" ::: "memory")
#define CP_WAIT_1()  asm volatile("cp.async.wait_group 1;" ::: "memory")
#define CP_WAIT_0()  asm volatile("cp.async.wait_group 0;" ::: "memory")

#define LDM_X4(r, addr) \
    asm volatile("ldmatrix.sync.aligned.m8n8.x4.shared.b16 {%0,%1,%2,%3}, [%4];" \
                 : "=r"((r)[0]), "=r"((r)[1]), "=r"((r)[2]), "=r"((r)[3]) : "r"(addr))

#define LDM_X4_T(r, addr) \
    asm volatile("ldmatrix.sync.aligned.m8n8.x4.trans.shared.b16 {%0,%1,%2,%3}, [%4];" \
                 : "=r"((r)[0]), "=r"((r)[1]), "=r"((r)[2]), "=r"((r)[3]) : "r"(addr))

#define MMA16816(c, a, b0, b1) \
    asm volatile("mma.sync.aligned.m16n8k16.row.col.f32.bf16.bf16.f32 " \
                 "{%0,%1,%2,%3}, {%4,%5,%6,%7}, {%8,%9}, {%0,%1,%2,%3};" \
                 : "+f"((c)[0]), "+f"((c)[1]), "+f"((c)[2]), "+f"((c)[3]) \
                 : "r"((a)[0]), "r"((a)[1]), "r"((a)[2]), "r"((a)[3]), \
                   "r"(b0), "r"(b1))

// split pair of floats into hi/lo bf16x2 regs (lo halfword = first element)
__device__ __forceinline__ void split2(float p0, float p1, uint32_t& hi, uint32_t& lo) {
    __nv_bfloat16 h0 = __float2bfloat16(p0), h1 = __float2bfloat16(p1);
    __nv_bfloat162 hh; hh.x = h0; hh.y = h1;
    hi = *reinterpret_cast<uint32_t*>(&hh);
    __nv_bfloat162 ll;
    ll.x = __float2bfloat16(p0 - __bfloat162float(h0));
    ll.y = __float2bfloat16(p1 - __bfloat162float(h1));
    lo = *reinterpret_cast<uint32_t*>(&ll);
}

// ================= operand conversion kernels ================================
__global__ __launch_bounds__(256) void convert_split_kernel(
    int total4, const float4* __restrict__ src,
    __nv_bfloat162* __restrict__ hi, __nv_bfloat162* __restrict__ lo)
{
    int i = blockIdx.x * blockDim.x + threadIdx.x;
    if (i >= total4) return;
    float4 v = src[i];
    __nv_bfloat16 hx = __float2bfloat16(v.x), hy = __float2bfloat16(v.y);
    __nv_bfloat16 hz = __float2bfloat16(v.z), hw = __float2bfloat16(v.w);
    hi[2 * i]     = __nv_bfloat162(hx, hy);
    hi[2 * i + 1] = __nv_bfloat162(hz, hw);
    lo[2 * i]     = __nv_bfloat162(__float2bfloat16(v.x - __bfloat162float(hx)),
                                   __float2bfloat16(v.y - __bfloat162float(hy)));
    lo[2 * i + 1] = __nv_bfloat162(__float2bfloat16(v.z - __bfloat162float(hz)),
                                   __float2bfloat16(v.w - __bfloat162float(hw)));
}

__global__ __launch_bounds__(256) void transpose_split_kernel(
    int K, int N, const float* __restrict__ W,
    __nv_bfloat16* __restrict__ Thi, __nv_bfloat16* __restrict__ Tlo)
{
    __shared__ float t[32][33];
    const int n0 = blockIdx.x * 32, k0 = blockIdx.y * 32;
    const int tx = threadIdx.x, ty = threadIdx.y;   // 32 x 8
#pragma unroll
    for (int j = 0; j < 4; j++) {
        int k = k0 + ty + j * 8;
        t[ty + j * 8][tx] = W[(size_t)k * N + n0 + tx];
    }
    __syncthreads();
#pragma unroll
    for (int j = 0; j < 4; j++) {
        int n = n0 + ty + j * 8;
        int k = k0 + tx;
        float v = t[tx][ty + j * 8];
        __nv_bfloat16 h = __float2bfloat16(v);
        Thi[(size_t)n * K + k] = h;
        Tlo[(size_t)n * K + k] = __float2bfloat16(v - __bfloat162float(h));
    }
}

// ================= mma.sync GEMM (unchanged from R6, passing) ================
#define GBK   32
#define PSTR  40
#define PART_SM  (128 * PSTR * 2)
#define STAGE_SM (4 * PART_SM)
#define GEMM_SMEM (2 * STAGE_SM)

__global__ __launch_bounds__(256) void gemm_mma_kernel(
    int K, int N,
    const __nv_bfloat16* __restrict__ Ahi, const __nv_bfloat16* __restrict__ Alo,
    const __nv_bfloat16* __restrict__ Bhi, const __nv_bfloat16* __restrict__ Blo,
    const float* __restrict__ bias, float* __restrict__ C)
{
    extern __shared__ char smem[];
    const uint32_t smb = smem_u32(smem);
    const int tid = threadIdx.x;
    const int lane = tid & 31;
    const int wid = tid >> 5;
    const int bx = blockIdx.x;
    const int by = blockIdx.y;
    const int wm = wid >> 1;
    const int wn = wid & 1;

    const __nv_bfloat16* src[4];
    src[0] = Ahi + (size_t)by * 128 * K;
    src[1] = Alo + (size_t)by * 128 * K;
    src[2] = Bhi + (size_t)bx * 128 * K;
    src[3] = Blo + (size_t)bx * 128 * K;

    const int lr = tid >> 1;
    const int lu = (tid & 1) * 2;

    float acc[2][8][4];
#pragma unroll
    for (int mt = 0; mt < 2; mt++)
#pragma unroll
        for (int nt = 0; nt < 8; nt++)
#pragma unroll
            for (int j = 0; j < 4; j++) acc[mt][nt][j] = 0.f;

    const int nch = K / GBK;
    {
        const uint32_t sb = smb;
#pragma unroll
        for (int p = 0; p < 4; p++) {
            const char* g = (const char*)(src[p] + (size_t)lr * K);
            uint32_t s = sb + p * PART_SM + lr * 80 + lu * 16;
            cp16(s,      g + lu * 16);
            cp16(s + 16, g + lu * 16 + 16);
        }
        CP_COMMIT();
    }

    for (int ch = 0; ch < nch; ch++) {
        if (ch + 1 < nch) {
            const uint32_t sb = smb + ((ch + 1) & 1) * STAGE_SM;
            const int koff = (ch + 1) * GBK;
#pragma unroll
            for (int p = 0; p < 4; p++) {
                const char* g = (const char*)(src[p] + (size_t)lr * K + koff);
                uint32_t s = sb + p * PART_SM + lr * 80 + lu * 16;
                cp16(s,      g + lu * 16);
                cp16(s + 16, g + lu * 16 + 16);
            }
            CP_COMMIT();
            CP_WAIT_1();
        } else {
            CP_WAIT_0();
        }
        __syncthreads();

        const uint32_t sb = smb + (ch & 1) * STAGE_SM;
#pragma unroll
        for (int ks = 0; ks < 2; ks++) {
            const int kb = ks * 16;
            uint32_t a[2][2][4];
#pragma unroll
            for (int pp = 0; pp < 2; pp++) {
#pragma unroll
                for (int mt = 0; mt < 2; mt++) {
                    int row = wm * 32 + mt * 16 + (lane & 15);
                    int kk  = kb + ((lane >> 4) & 1) * 8;
                    uint32_t ad = sb + pp * PART_SM + row * 80 + kk * 2;
                    LDM_X4(a[pp][mt], ad);
                }
            }
#pragma unroll
            for (int np = 0; np < 4; np++) {
                int rowb = wn * 64 + np * 16 + (lane & 7) + ((lane >> 4) & 1) * 8;
                int kk   = kb + ((lane >> 3) & 1) * 8;
                uint32_t bh[4], bl[4];
                LDM_X4(bh, sb + 2 * PART_SM + rowb * 80 + kk * 2);
                LDM_X4(bl, sb + 3 * PART_SM + rowb * 80 + kk * 2);
#pragma unroll
                for (int half = 0; half < 2; half++) {
                    const int nt = np * 2 + half;
                    const uint32_t b0h = bh[half * 2], b1h = bh[half * 2 + 1];
                    const uint32_t b0l = bl[half * 2], b1l = bl[half * 2 + 1];
#pragma unroll
                    for (int mt = 0; mt < 2; mt++) {
                        MMA16816(acc[mt][nt], a[0][mt], b0h, b1h);
                        MMA16816(acc[mt][nt], a[0][mt], b0l, b1l);
                        MMA16816(acc[mt][nt], a[1][mt], b0h, b1h);
                    }
                }
            }
        }
        __syncthreads();
    }

    const int gq = lane >> 2;
    const int cn = (lane & 3) * 2;
#pragma unroll
    for (int mt = 0; mt < 2; mt++) {
        const int row = by * 128 + wm * 32 + mt * 16 + gq;
#pragma unroll
        for (int nt = 0; nt < 8; nt++) {
            const int col = bx * 128 + wn * 64 + nt * 8 + cn;
            const float2 bb = *(const float2*)(bias + col);
            float2 o0, o1;
            o0.x = acc[mt][nt][0] + bb.x;
            o0.y = acc[mt][nt][1] + bb.y;
            o1.x = acc[mt][nt][2] + bb.x;
            o1.y = acc[mt][nt][3] + bb.y;
            *(float2*)(C + (size_t)row * N + col)       = o0;
            *(float2*)(C + (size_t)(row + 8) * N + col) = o1;
        }
    }
}

// ---------------- RoPE + scatter to [B,H,T,hd], bf16 hi/lo split -------------
__device__ __forceinline__ void store_split(__nv_bfloat16* hi, __nv_bfloat16* lo,
                                            size_t o, float v) {
    __nv_bfloat16 h = __float2bfloat16(v);
    hi[o] = h;
    lo[o] = __float2bfloat16(v - __bfloat162float(h));
}

__global__ __launch_bounds__(256) void rope_split_kernel(
    const float* __restrict__ qkv,
    __nv_bfloat16* __restrict__ qhi, __nv_bfloat16* __restrict__ qlo,
    __nv_bfloat16* __restrict__ khi, __nv_bfloat16* __restrict__ klo,
    __nv_bfloat16* __restrict__ vhi, __nv_bfloat16* __restrict__ vlo)
{
    int idx = blockIdx.x * blockDim.x + threadIdx.x;
    const int total = BATCH * SEQ * NHEAD * (HD / 2);
    if (idx >= total) return;

    const int d2 = idx & 31;
    const int h  = (idx >> 5) & 15;
    const int t  = (idx >> 9) & (SEQ - 1);
    const int b  = idx >> 20;

    const float* row = qkv + ((size_t)(b * SEQ + t)) * C3;
    const float theta = __powf(10000.0f, -(2.0f * d2) / 64.0f);
    float s, c;
    sincosf((float)h * theta, &s, &c);

    const size_t o = (((size_t)(b * NHEAD + h)) * SEQ + t) * HD + 2 * d2;
    const int qc = h * HD + 2 * d2;

    float q0 = row[qc], q1 = row[qc + 1];
    store_split(qhi, qlo, o,     q0 * c - q1 * s);
    store_split(qhi, qlo, o + 1, q1 * c + q0 * s);

    float k0 = row[CDIM + qc], k1 = row[CDIM + qc + 1];
    store_split(khi, klo, o,     k0 * c - k1 * s);
    store_split(khi, klo, o + 1, k1 * c + k0 * s);

    store_split(vhi, vlo, o,     row[2 * CDIM + qc]);
    store_split(vhi, vlo, o + 1, row[2 * CDIM + qc + 1]);
}

// ---------------- Flash attention (causal), mma.sync bf16 split --------------
// CTA: 128 q rows (8 warps x m16), K/V tiles 64 rows, double-buffered cp.async.
#define AKSTRB 144                   // 72 bf16 row stride in bytes
#define APART  (64 * AKSTRB)         // 9216 B (one 64x64 operand part)
#define ASTAGE (4 * APART)           // 36864 B  (Khi,Klo,Vhi,Vlo)
#define ATTN_SMEM (2 * ASTAGE)       // 73728 B

__global__ __launch_bounds__(256, 1) void attn_mma_kernel(
    const __nv_bfloat16* __restrict__ Qhi, const __nv_bfloat16* __restrict__ Qlo,
    const __nv_bfloat16* __restrict__ Khi, const __nv_bfloat16* __restrict__ Klo,
    const __nv_bfloat16* __restrict__ Vhi, const __nv_bfloat16* __restrict__ Vlo,
    float* __restrict__ Y)
{
    extern __shared__ char smem[];
    const uint32_t smb = smem_u32(smem);
    const int tid = threadIdx.x, lane = tid & 31, wid = tid >> 5;
    const int qt = blockIdx.x, h = blockIdx.y, b = blockIdx.z;
    const int qbase = qt * 128;
    const size_t headOff = ((size_t)(b * NHEAD + h)) * SEQ * HD;

    // ---- stage Q (hi at stage0+0, lo at stage0+APART*2) and load fragments ----
    {
        const int part = tid >> 7;      // 0..1
        const int row  = tid & 127;
        const __nv_bfloat16* gq = (part == 0 ? Qhi : Qlo) + headOff + (size_t)(qbase + row) * HD;
        uint32_t s = smb + part * (128 * AKSTRB) + 0;   // Qlo block right after Qhi block
        s = smb + part * 18432 + row * AKSTRB;
#pragma unroll
        for (int u = 0; u < 8; u++) cp16(s + u * 16, (const char*)gq + u * 16);
        CP_COMMIT();
        CP_WAIT_0();
    }
    __syncthreads();

    uint32_t qh[4][4], ql[4][4];
    {
        const int row = wid * 16 + (lane & 15);
        const int ko  = ((lane >> 4) & 1) * 8;
#pragma unroll
        for (int kb = 0; kb < 4; kb++) {
            uint32_t ad = smb + row * AKSTRB + (kb * 16 + ko) * 2;
            LDM_X4(qh[kb], ad);
            LDM_X4(ql[kb], ad + 18432);
        }
    }
    __syncthreads();

    // ---- softmax state + O accumulators (registers) ----
    float m0 = -1e30f, m1 = -1e30f, l0 = 0.f, l1 = 0.f;
    float Oacc[8][4];
#pragma unroll
    for (int nt = 0; nt < 8; nt++)
#pragma unroll
        for (int j = 0; j < 4; j++) Oacc[nt][j] = 0.f;

    const int nkt = 2 * qt + 2;
    const int ldp  = tid >> 6;       // 0..3: Khi,Klo,Vhi,Vlo
    const int ldr  = tid & 63;
    const __nv_bfloat16* ldsrc =
        (ldp == 0 ? Khi : ldp == 1 ? Klo : ldp == 2 ? Vhi : Vlo) + headOff;

    // prologue: kt = 0 -> stage 0
    {
        const char* g = (const char*)(ldsrc + (size_t)ldr * HD);
        uint32_t s = smb + ldp * APART + ldr * AKSTRB;
#pragma unroll
        for (int u = 0; u < 8; u++) cp16(s + u * 16, g + u * 16);
        CP_COMMIT();
    }

    const int gq = lane >> 2;
    const int c2 = (lane & 3) * 2;

    for (int kt = 0; kt < nkt; kt++) {
        if (kt + 1 < nkt) {
            const char* g = (const char*)(ldsrc + (size_t)((kt + 1) * 64 + ldr) * HD);
            uint32_t s = smb + ((kt + 1) & 1) * ASTAGE + ldp * APART + ldr * AKSTRB;
#pragma unroll
            for (int u = 0; u < 8; u++) cp16(s + u * 16, g + u * 16);
            CP_COMMIT();
            CP_WAIT_1();
        } else {
            CP_WAIT_0();
        }
        __syncthreads();

        const uint32_t sb = smb + (kt & 1) * ASTAGE;
        const int ktbase = kt * 64;
        // warp-tile causal skip (loads/syncs stay uniform)
        if (ktbase <= qbase + wid * 16 + 15) {
            // ---- S = Q K^T (split: hi*hi + hi*lo + lo*hi) ----
            float acc[8][4];
#pragma unroll
            for (int nt = 0; nt < 8; nt++)
#pragma unroll
                for (int j = 0; j < 4; j++) acc[nt][j] = 0.f;

#pragma unroll
            for (int kb = 0; kb < 4; kb++) {
#pragma unroll
                for (int np = 0; np < 4; np++) {
                    const int nrow = np * 16 + (lane & 7) + ((lane >> 4) & 1) * 8;
                    const int kcol = kb * 16 + ((lane >> 3) & 1) * 8;
                    uint32_t kh[4], kl[4];
                    const uint32_t ad = sb + nrow * AKSTRB + kcol * 2;
                    LDM_X4(kh, ad);
                    LDM_X4(kl, ad + APART);
#pragma unroll
                    for (int half = 0; half < 2; half++) {
                        const int nt = np * 2 + half;
                        MMA16816(acc[nt], qh[kb], kh[2 * half], kh[2 * half + 1]);
                        MMA16816(acc[nt], qh[kb], kl[2 * half], kl[2 * half + 1]);
                        MMA16816(acc[nt], ql[kb], kh[2 * half], kh[2 * half + 1]);
                    }
                }
            }

            // ---- scale + causal mask ----
            const int row0 = qbase + wid * 16 + gq;
            const int row1 = row0 + 8;
            if (ktbase + 63 > qbase + wid * 16) {
#pragma unroll
                for (int nt = 0; nt < 8; nt++) {
#pragma unroll
                    for (int j = 0; j < 4; j++) {
                        const int col = ktbase + nt * 8 + c2 + (j & 1);
                        const int r   = (j < 2) ? row0 : row1;
                        float sv = acc[nt][j] * 0.125f;
                        if (col > r) sv = -1e30f;
                        acc[nt][j] = sv;
                    }
                }
            } else {
#pragma unroll
                for (int nt = 0; nt < 8; nt++)
#pragma unroll
                    for (int j = 0; j < 4; j++) acc[nt][j] *= 0.125f;
            }

            // ---- online softmax (register state) ----
            float mx0 = -1e30f, mx1 = -1e30f;
#pragma unroll
            for (int nt = 0; nt < 8; nt++) {
                mx0 = fmaxf(mx0, fmaxf(acc[nt][0], acc[nt][1]));
                mx1 = fmaxf(mx1, fmaxf(acc[nt][2], acc[nt][3]));
            }
            mx0 = fmaxf(mx0, __shfl_xor_sync(0xffffffffu, mx0, 1));
            mx0 = fmaxf(mx0, __shfl_xor_sync(0xffffffffu, mx0, 2));
            mx1 = fmaxf(mx1, __shfl_xor_sync(0xffffffffu, mx1, 1));
            mx1 = fmaxf(mx1, __shfl_xor_sync(0xffffffffu, mx1, 2));

            const float mn0 = fmaxf(m0, mx0), mn1 = fmaxf(m1, mx1);
            const float al0 = __expf(m0 - mn0), al1 = __expf(m1 - mn1);
            float s0 = 0.f, s1 = 0.f;
#pragma unroll
            for (int nt = 0; nt < 8; nt++) {
                float p0 = __expf(acc[nt][0] - mn0);
                float p1 = __expf(acc[nt][1] - mn0);
                float p2 = __expf(acc[nt][2] - mn1);
                float p3 = __expf(acc[nt][3] - mn1);
                acc[nt][0] = p0; acc[nt][1] = p1; acc[nt][2] = p2; acc[nt][3] = p3;
                s0 += p0 + p1;
                s1 += p2 + p3;
            }
            s0 += __shfl_xor_sync(0xffffffffu, s0, 1);
            s0 += __shfl_xor_sync(0xffffffffu, s0, 2);
            s1 += __shfl_xor_sync(0xffffffffu, s1, 1);
            s1 += __shfl_xor_sync(0xffffffffu, s1, 2);
            l0 = l0 * al0 + s0;
            l1 = l1 * al1 + s1;
            m0 = mn0; m1 = mn1;
#pragma unroll
            for (int nt = 0; nt < 8; nt++) {
                Oacc[nt][0] *= al0; Oacc[nt][1] *= al0;
                Oacc[nt][2] *= al1; Oacc[nt][3] *= al1;
            }

            // ---- O += P V (split: Phi*Vhi + Phi*Vlo + Plo*Vhi) ----
#pragma unroll
            for (int kb = 0; kb < 4; kb++) {
                uint32_t ph[4], pl[4];
                split2(acc[2 * kb][0],     acc[2 * kb][1],     ph[0], pl[0]);
                split2(acc[2 * kb][2],     acc[2 * kb][3],     ph[1], pl[1]);
                split2(acc[2 * kb + 1][0], acc[2 * kb + 1][1], ph[2], pl[2]);
                split2(acc[2 * kb + 1][2], acc[2 * kb + 1][3], ph[3], pl[3]);
                const int krow = kb * 16 + (lane & 7) + ((lane >> 3) & 1) * 8;
#pragma unroll
                for (int np = 0; np < 4; np++) {
                    const int ncol = np * 16 + ((lane >> 4) & 1) * 8;
                    uint32_t vh[4], vl[4];
                    const uint32_t ad = sb + 2 * APART + krow * AKSTRB + ncol * 2;
                    LDM_X4_T(vh, ad);
                    LDM_X4_T(vl, ad + APART);
#pragma unroll
                    for (int half = 0; half < 2; half++) {
                        const int nt = np * 2 + half;
                        MMA16816(Oacc[nt], ph, vh[2 * half], vh[2 * half + 1]);
                        MMA16816(Oacc[nt], ph, vl[2 * half], vl[2 * half + 1]);
                        MMA16816(Oacc[nt], pl, vh[2 * half], vh[2 * half + 1]);
                    }
                }
            }
        }
        __syncthreads();
    }

    // ---- epilogue: normalize and store to Y[B,T,C] ----
    const float inv0 = 1.0f / l0, inv1 = 1.0f / l1;
    const int r0 = qbase + wid * 16 + gq;
    float* y0 = Y + ((size_t)b * SEQ + r0) * CDIM + h * HD;
    float* y1 = y0 + 8 * CDIM;
#pragma unroll
    for (int nt = 0; nt < 8; nt++) {
        float2 a, c;
        a.x = Oacc[nt][0] * inv0; a.y = Oacc[nt][1] * inv0;
        c.x = Oacc[nt][2] * inv1; c.y = Oacc[nt][3] * inv1;
        *(float2*)(y0 + nt * 8 + c2) = a;
        *(float2*)(y1 + nt * 8 + c2) = c;
    }
}

// ---------------- launch ----------------------------------------------------
extern "C" void kernel_launch(void* const* d_in, const int* in_sizes, int n_in,
                              void* d_out, int out_size)
{
    const float* x      = (const float*)d_in[0];
    const float* W_attn = (const float*)d_in[1];
    const float* b_attn = (const float*)d_in[2];
    const float* W_proj = (const float*)d_in[3];
    const float* b_proj = (const float*)d_in[4];
    float* out = (float*)d_out;

    float *qkv, *y;
    __nv_bfloat16 *ahi, *alo, *w1hi, *w1lo, *w2hi, *w2lo;
    __nv_bfloat16 *qhi, *qlo, *khi, *klo, *vhi, *vlo;
    cudaGetSymbolAddress((void**)&qkv,  g_qkv);
    cudaGetSymbolAddress((void**)&y,    g_y);
    cudaGetSymbolAddress((void**)&ahi,  g_ahi);
    cudaGetSymbolAddress((void**)&alo,  g_alo);
    cudaGetSymbolAddress((void**)&w1hi, g_w1hi);
    cudaGetSymbolAddress((void**)&w1lo, g_w1lo);
    cudaGetSymbolAddress((void**)&w2hi, g_w2hi);
    cudaGetSymbolAddress((void**)&w2lo, g_w2lo);
    cudaGetSymbolAddress((void**)&qhi,  g_qhi);
    cudaGetSymbolAddress((void**)&qlo,  g_qlo);
    cudaGetSymbolAddress((void**)&khi,  g_khi);
    cudaGetSymbolAddress((void**)&klo,  g_klo);
    cudaGetSymbolAddress((void**)&vhi,  g_vhi);
    cudaGetSymbolAddress((void**)&vlo,  g_vlo);

    cudaFuncSetAttribute(gemm_mma_kernel,
                         cudaFuncAttributeMaxDynamicSharedMemorySize, GEMM_SMEM);
    cudaFuncSetAttribute(attn_mma_kernel,
                         cudaFuncAttributeMaxDynamicSharedMemorySize, ATTN_SMEM);

    // convert weights (transpose + split)
    {
        dim3 blk(32, 8);
        dim3 g1(C3 / 32, CDIM / 32);
        transpose_split_kernel<<<g1, blk>>>(CDIM, C3, W_attn, w1hi, w1lo);
        dim3 g2(CDIM / 32, CDIM / 32);
        transpose_split_kernel<<<g2, blk>>>(CDIM, CDIM, W_proj, w2hi, w2lo);
    }
    // convert x
    {
        int total4 = MROWS * CDIM / 4;
        convert_split_kernel<<<(total4 + 255) / 256, 256>>>(
            total4, (const float4*)x, (__nv_bfloat162*)ahi, (__nv_bfloat162*)alo);
    }
    // GEMM1: qkv = x @ W_attn + b_attn
    {
        dim3 grid(C3 / 128, MROWS / 128);
        gemm_mma_kernel<<<grid, 256, GEMM_SMEM>>>(CDIM, C3,
                                                  ahi, alo, w1hi, w1lo, b_attn, qkv);
    }
    // RoPE + scatter + split
    {
        int total = BATCH * SEQ * NHEAD * (HD / 2);
        rope_split_kernel<<<(total + 255) / 256, 256>>>(qkv, qhi, qlo, khi, klo, vhi, vlo);
    }
    // Flash attention (tensor cores)
    {
        dim3 grid(SEQ / 128, NHEAD, BATCH);
        attn_mma_kernel<<<grid, 256, ATTN_SMEM>>>(qhi, qlo, khi, klo, vhi, vlo, y);
    }
    // convert y
    {
        int total4 = MROWS * CDIM / 4;
        convert_split_kernel<<<(total4 + 255) / 256, 256>>>(
            total4, (const float4*)y, (__nv_bfloat162*)ahi, (__nv_bfloat162*)alo);
    }
    // GEMM2: out = y @ W_proj + b_proj
    {
        dim3 grid(CDIM / 128, MROWS / 128);
        gemm_mma_kernel<<<grid, 256, GEMM_SMEM>>>(CDIM, CDIM,
                                                  ahi, alo, w2hi, w2lo, b_proj, out);
    }
}

// round 14
// speedup vs baseline: 2.9569x; 1.1255x over previous
#include <cuda_runtime.h>
#include <cuda_bf16.h>
#include <cstdint>

// Problem constants
#define BATCH 2
#define SEQ   2048
#define CDIM  1024
#define NHEAD 16
#define HD    64
#define C3    3072
#define MROWS (BATCH * SEQ)   // 4096

// ---------------- scratch (device globals; no allocation allowed) -----------
__device__ float g_qkv[BATCH * SEQ * C3];

// bf16 split-precision operand scratch
__device__ __nv_bfloat16 g_ahi[MROWS * CDIM];
__device__ __nv_bfloat16 g_alo[MROWS * CDIM];
__device__ __nv_bfloat16 g_w1hi[C3 * CDIM];
__device__ __nv_bfloat16 g_w1lo[C3 * CDIM];
__device__ __nv_bfloat16 g_w2hi[CDIM * CDIM];
__device__ __nv_bfloat16 g_w2lo[CDIM * CDIM];

// attention operands, [B,H,T,hd] bf16 hi/lo
#define QKV_ELEMS (BATCH * NHEAD * SEQ * HD)
__device__ __nv_bfloat16 g_qhi[QKV_ELEMS];
__device__ __nv_bfloat16 g_qlo[QKV_ELEMS];
__device__ __nv_bfloat16 g_khi[QKV_ELEMS];
__device__ __nv_bfloat16 g_klo[QKV_ELEMS];
__device__ __nv_bfloat16 g_vhi[QKV_ELEMS];
__device__ __nv_bfloat16 g_vlo[QKV_ELEMS];

// ================= PTX helpers (plain sm_80+ PTX only) =======================
__device__ __forceinline__ uint32_t smem_u32(const void* p) {
    uint32_t a;
    asm("{ .reg .u64 tmp; cvta.to.shared.u64 tmp, %1; cvt.u32.u64 %0, tmp; }"
        : "=r"(a) : "l"(p));
    return a;
}
__device__ __forceinline__ void cp16(uint32_t s, const void* g) {
    asm volatile("cp.async.cg.shared.global [%0], [%1], 16;" :: "r"(s), "l"(g));
}
#define CP_COMMIT()  asm volatile("cp.async.commit_group;" ::: "memory")
#define CP_WAIT_1()  asm volatile("cp.async.wait_group 1;" ::: "memory")
#define CP_WAIT_0()  asm volatile("cp.async.wait_group 0;" ::: "memory")

#define LDM_X4(r, addr) \
    asm volatile("ldmatrix.sync.aligned.m8n8.x4.shared.b16 {%0,%1,%2,%3}, [%4];" \
                 : "=r"((r)[0]), "=r"((r)[1]), "=r"((r)[2]), "=r"((r)[3]) : "r"(addr))

#define LDM_X4_T(r, addr) \
    asm volatile("ldmatrix.sync.aligned.m8n8.x4.trans.shared.b16 {%0,%1,%2,%3}, [%4];" \
                 : "=r"((r)[0]), "=r"((r)[1]), "=r"((r)[2]), "=r"((r)[3]) : "r"(addr))

#define MMA16816(c, a, b0, b1) \
    asm volatile("mma.sync.aligned.m16n8k16.row.col.f32.bf16.bf16.f32 " \
                 "{%0,%1,%2,%3}, {%4,%5,%6,%7}, {%8,%9}, {%0,%1,%2,%3};" \
                 : "+f"((c)[0]), "+f"((c)[1]), "+f"((c)[2]), "+f"((c)[3]) \
                 : "r"((a)[0]), "r"((a)[1]), "r"((a)[2]), "r"((a)[3]), \
                   "r"(b0), "r"(b1))

// split pair of floats into hi/lo bf16x2 regs (lo halfword = first element)
__device__ __forceinline__ void split2(float p0, float p1, uint32_t& hi, uint32_t& lo) {
    __nv_bfloat16 h0 = __float2bfloat16(p0), h1 = __float2bfloat16(p1);
    __nv_bfloat162 hh; hh.x = h0; hh.y = h1;
    hi = *reinterpret_cast<uint32_t*>(&hh);
    __nv_bfloat162 ll;
    ll.x = __float2bfloat16(p0 - __bfloat162float(h0));
    ll.y = __float2bfloat16(p1 - __bfloat162float(h1));
    lo = *reinterpret_cast<uint32_t*>(&ll);
}

// ================= operand conversion kernels ================================
__global__ __launch_bounds__(256) void convert_split_kernel(
    int total4, const float4* __restrict__ src,
    __nv_bfloat162* __restrict__ hi, __nv_bfloat162* __restrict__ lo)
{
    int i = blockIdx.x * blockDim.x + threadIdx.x;
    if (i >= total4) return;
    float4 v = src[i];
    __nv_bfloat16 hx = __float2bfloat16(v.x), hy = __float2bfloat16(v.y);
    __nv_bfloat16 hz = __float2bfloat16(v.z), hw = __float2bfloat16(v.w);
    hi[2 * i]     = __nv_bfloat162(hx, hy);
    hi[2 * i + 1] = __nv_bfloat162(hz, hw);
    lo[2 * i]     = __nv_bfloat162(__float2bfloat16(v.x - __bfloat162float(hx)),
                                   __float2bfloat16(v.y - __bfloat162float(hy)));
    lo[2 * i + 1] = __nv_bfloat162(__float2bfloat16(v.z - __bfloat162float(hz)),
                                   __float2bfloat16(v.w - __bfloat162float(hw)));
}

__global__ __launch_bounds__(256) void transpose_split_kernel(
    int K, int N, const float* __restrict__ W,
    __nv_bfloat16* __restrict__ Thi, __nv_bfloat16* __restrict__ Tlo)
{
    __shared__ float t[32][33];
    const int n0 = blockIdx.x * 32, k0 = blockIdx.y * 32;
    const int tx = threadIdx.x, ty = threadIdx.y;   // 32 x 8
#pragma unroll
    for (int j = 0; j < 4; j++) {
        int k = k0 + ty + j * 8;
        t[ty + j * 8][tx] = W[(size_t)k * N + n0 + tx];
    }
    __syncthreads();
#pragma unroll
    for (int j = 0; j < 4; j++) {
        int n = n0 + ty + j * 8;
        int k = k0 + tx;
        float v = t[tx][ty + j * 8];
        __nv_bfloat16 h = __float2bfloat16(v);
        Thi[(size_t)n * K + k] = h;
        Tlo[(size_t)n * K + k] = __float2bfloat16(v - __bfloat162float(h));
    }
}

// ================= mma.sync GEMM: C[M,N] = A[M,K] @ Bt[N,K]^T + bias =========
#define GBK   32
#define PSTR  40
#define PART_SM  (128 * PSTR * 2)
#define STAGE_SM (4 * PART_SM)
#define GEMM_SMEM (2 * STAGE_SM)

__global__ __launch_bounds__(256, 2) void gemm_mma_kernel(
    int K, int N,
    const __nv_bfloat16* __restrict__ Ahi, const __nv_bfloat16* __restrict__ Alo,
    const __nv_bfloat16* __restrict__ Bhi, const __nv_bfloat16* __restrict__ Blo,
    const float* __restrict__ bias, float* __restrict__ C)
{
    extern __shared__ char smem[];
    const uint32_t smb = smem_u32(smem);
    const int tid = threadIdx.x;
    const int lane = tid & 31;
    const int wid = tid >> 5;
    const int bx = blockIdx.x;
    const int by = blockIdx.y;
    const int wm = wid >> 1;
    const int wn = wid & 1;

    const __nv_bfloat16* src[4];
    src[0] = Ahi + (size_t)by * 128 * K;
    src[1] = Alo + (size_t)by * 128 * K;
    src[2] = Bhi + (size_t)bx * 128 * K;
    src[3] = Blo + (size_t)bx * 128 * K;

    const int lr = tid >> 1;
    const int lu = (tid & 1) * 2;

    float acc[2][8][4];
#pragma unroll
    for (int mt = 0; mt < 2; mt++)
#pragma unroll
        for (int nt = 0; nt < 8; nt++)
#pragma unroll
            for (int j = 0; j < 4; j++) acc[mt][nt][j] = 0.f;

    const int nch = K / GBK;
    {
        const uint32_t sb = smb;
#pragma unroll
        for (int p = 0; p < 4; p++) {
            const char* g = (const char*)(src[p] + (size_t)lr * K);
            uint32_t s = sb + p * PART_SM + lr * 80 + lu * 16;
            cp16(s,      g + lu * 16);
            cp16(s + 16, g + lu * 16 + 16);
        }
        CP_COMMIT();
    }

    for (int ch = 0; ch < nch; ch++) {
        if (ch + 1 < nch) {
            const uint32_t sb = smb + ((ch + 1) & 1) * STAGE_SM;
            const int koff = (ch + 1) * GBK;
#pragma unroll
            for (int p = 0; p < 4; p++) {
                const char* g = (const char*)(src[p] + (size_t)lr * K + koff);
                uint32_t s = sb + p * PART_SM + lr * 80 + lu * 16;
                cp16(s,      g + lu * 16);
                cp16(s + 16, g + lu * 16 + 16);
            }
            CP_COMMIT();
            CP_WAIT_1();
        } else {
            CP_WAIT_0();
        }
        __syncthreads();

        const uint32_t sb = smb + (ch & 1) * STAGE_SM;
#pragma unroll
        for (int ks = 0; ks < 2; ks++) {
            const int kb = ks * 16;
            uint32_t a[2][2][4];
#pragma unroll
            for (int pp = 0; pp < 2; pp++) {
#pragma unroll
                for (int mt = 0; mt < 2; mt++) {
                    int row = wm * 32 + mt * 16 + (lane & 15);
                    int kk  = kb + ((lane >> 4) & 1) * 8;
                    uint32_t ad = sb + pp * PART_SM + row * 80 + kk * 2;
                    LDM_X4(a[pp][mt], ad);
                }
            }
#pragma unroll
            for (int np = 0; np < 4; np++) {
                int rowb = wn * 64 + np * 16 + (lane & 7) + ((lane >> 4) & 1) * 8;
                int kk   = kb + ((lane >> 3) & 1) * 8;
                uint32_t bh[4], bl[4];
                LDM_X4(bh, sb + 2 * PART_SM + rowb * 80 + kk * 2);
                LDM_X4(bl, sb + 3 * PART_SM + rowb * 80 + kk * 2);
#pragma unroll
                for (int half = 0; half < 2; half++) {
                    const int nt = np * 2 + half;
                    const uint32_t b0h = bh[half * 2], b1h = bh[half * 2 + 1];
                    const uint32_t b0l = bl[half * 2], b1l = bl[half * 2 + 1];
#pragma unroll
                    for (int mt = 0; mt < 2; mt++) {
                        MMA16816(acc[mt][nt], a[0][mt], b0h, b1h);
                        MMA16816(acc[mt][nt], a[0][mt], b0l, b1l);
                        MMA16816(acc[mt][nt], a[1][mt], b0h, b1h);
                    }
                }
            }
        }
        __syncthreads();
    }

    const int gq = lane >> 2;
    const int cn = (lane & 3) * 2;
#pragma unroll
    for (int mt = 0; mt < 2; mt++) {
        const int row = by * 128 + wm * 32 + mt * 16 + gq;
#pragma unroll
        for (int nt = 0; nt < 8; nt++) {
            const int col = bx * 128 + wn * 64 + nt * 8 + cn;
            const float2 bb = *(const float2*)(bias + col);
            float2 o0, o1;
            o0.x = acc[mt][nt][0] + bb.x;
            o0.y = acc[mt][nt][1] + bb.y;
            o1.x = acc[mt][nt][2] + bb.x;
            o1.y = acc[mt][nt][3] + bb.y;
            *(float2*)(C + (size_t)row * N + col)       = o0;
            *(float2*)(C + (size_t)(row + 8) * N + col) = o1;
        }
    }
}

// ---------------- RoPE + scatter to [B,H,T,hd], bf16 hi/lo split -------------
__device__ __forceinline__ void store_split(__nv_bfloat16* hi, __nv_bfloat16* lo,
                                            size_t o, float v) {
    __nv_bfloat16 h = __float2bfloat16(v);
    hi[o] = h;
    lo[o] = __float2bfloat16(v - __bfloat162float(h));
}

__global__ __launch_bounds__(256) void rope_split_kernel(
    const float* __restrict__ qkv,
    __nv_bfloat16* __restrict__ qhi, __nv_bfloat16* __restrict__ qlo,
    __nv_bfloat16* __restrict__ khi, __nv_bfloat16* __restrict__ klo,
    __nv_bfloat16* __restrict__ vhi, __nv_bfloat16* __restrict__ vlo)
{
    int idx = blockIdx.x * blockDim.x + threadIdx.x;
    const int total = BATCH * SEQ * NHEAD * (HD / 2);
    if (idx >= total) return;

    const int d2 = idx & 31;
    const int h  = (idx >> 5) & 15;
    const int t  = (idx >> 9) & (SEQ - 1);
    const int b  = idx >> 20;

    const float* row = qkv + ((size_t)(b * SEQ + t)) * C3;
    const float theta = __powf(10000.0f, -(2.0f * d2) / 64.0f);
    float s, c;
    sincosf((float)h * theta, &s, &c);

    const size_t o = (((size_t)(b * NHEAD + h)) * SEQ + t) * HD + 2 * d2;
    const int qc = h * HD + 2 * d2;

    float q0 = row[qc], q1 = row[qc + 1];
    store_split(qhi, qlo, o,     q0 * c - q1 * s);
    store_split(qhi, qlo, o + 1, q1 * c + q0 * s);

    float k0 = row[CDIM + qc], k1 = row[CDIM + qc + 1];
    store_split(khi, klo, o,     k0 * c - k1 * s);
    store_split(khi, klo, o + 1, k1 * c + k0 * s);

    store_split(vhi, vlo, o,     row[2 * CDIM + qc]);
    store_split(vhi, vlo, o + 1, row[2 * CDIM + qc + 1]);
}

// ---------------- Flash attention (causal), mma.sync bf16 split --------------
// CTA: 128 q rows (8 warps x m16), K/V tiles 64 rows, double-buffered cp.async.
// Epilogue writes split bf16 directly into activation buffers for GEMM2.
#define AKSTRB 144
#define APART  (64 * AKSTRB)
#define ASTAGE (4 * APART)
#define ATTN_SMEM (2 * ASTAGE)

__global__ __launch_bounds__(256, 1) void attn_mma_kernel(
    const __nv_bfloat16* __restrict__ Qhi, const __nv_bfloat16* __restrict__ Qlo,
    const __nv_bfloat16* __restrict__ Khi, const __nv_bfloat16* __restrict__ Klo,
    const __nv_bfloat16* __restrict__ Vhi, const __nv_bfloat16* __restrict__ Vlo,
    __nv_bfloat16* __restrict__ Yhi, __nv_bfloat16* __restrict__ Ylo)
{
    extern __shared__ char smem[];
    const uint32_t smb = smem_u32(smem);
    const int tid = threadIdx.x, lane = tid & 31, wid = tid >> 5;
    const int qt = blockIdx.x, h = blockIdx.y, b = blockIdx.z;
    const int qbase = qt * 128;
    const size_t headOff = ((size_t)(b * NHEAD + h)) * SEQ * HD;

    // ---- stage Q and load fragments ----
    {
        const int part = tid >> 7;
        const int row  = tid & 127;
        const __nv_bfloat16* gq = (part == 0 ? Qhi : Qlo) + headOff + (size_t)(qbase + row) * HD;
        uint32_t s = smb + part * 18432 + row * AKSTRB;
#pragma unroll
        for (int u = 0; u < 8; u++) cp16(s + u * 16, (const char*)gq + u * 16);
        CP_COMMIT();
        CP_WAIT_0();
    }
    __syncthreads();

    uint32_t qh[4][4], ql[4][4];
    {
        const int row = wid * 16 + (lane & 15);
        const int ko  = ((lane >> 4) & 1) * 8;
#pragma unroll
        for (int kb = 0; kb < 4; kb++) {
            uint32_t ad = smb + row * AKSTRB + (kb * 16 + ko) * 2;
            LDM_X4(qh[kb], ad);
            LDM_X4(ql[kb], ad + 18432);
        }
    }
    __syncthreads();

    float m0 = -1e30f, m1 = -1e30f, l0 = 0.f, l1 = 0.f;
    float Oacc[8][4];
#pragma unroll
    for (int nt = 0; nt < 8; nt++)
#pragma unroll
        for (int j = 0; j < 4; j++) Oacc[nt][j] = 0.f;

    const int nkt = 2 * qt + 2;
    const int ldp  = tid >> 6;
    const int ldr  = tid & 63;
    const __nv_bfloat16* ldsrc =
        (ldp == 0 ? Khi : ldp == 1 ? Klo : ldp == 2 ? Vhi : Vlo) + headOff;

    {
        const char* g = (const char*)(ldsrc + (size_t)ldr * HD);
        uint32_t s = smb + ldp * APART + ldr * AKSTRB;
#pragma unroll
        for (int u = 0; u < 8; u++) cp16(s + u * 16, g + u * 16);
        CP_COMMIT();
    }

    const int gq = lane >> 2;
    const int c2 = (lane & 3) * 2;

    for (int kt = 0; kt < nkt; kt++) {
        if (kt + 1 < nkt) {
            const char* g = (const char*)(ldsrc + (size_t)((kt + 1) * 64 + ldr) * HD);
            uint32_t s = smb + ((kt + 1) & 1) * ASTAGE + ldp * APART + ldr * AKSTRB;
#pragma unroll
            for (int u = 0; u < 8; u++) cp16(s + u * 16, g + u * 16);
            CP_COMMIT();
            CP_WAIT_1();
        } else {
            CP_WAIT_0();
        }
        __syncthreads();

        const uint32_t sb = smb + (kt & 1) * ASTAGE;
        const int ktbase = kt * 64;
        if (ktbase <= qbase + wid * 16 + 15) {
            float acc[8][4];
#pragma unroll
            for (int nt = 0; nt < 8; nt++)
#pragma unroll
                for (int j = 0; j < 4; j++) acc[nt][j] = 0.f;

#pragma unroll
            for (int kb = 0; kb < 4; kb++) {
#pragma unroll
                for (int np = 0; np < 4; np++) {
                    const int nrow = np * 16 + (lane & 7) + ((lane >> 4) & 1) * 8;
                    const int kcol = kb * 16 + ((lane >> 3) & 1) * 8;
                    uint32_t kh[4], kl[4];
                    const uint32_t ad = sb + nrow * AKSTRB + kcol * 2;
                    LDM_X4(kh, ad);
                    LDM_X4(kl, ad + APART);
#pragma unroll
                    for (int half = 0; half < 2; half++) {
                        const int nt = np * 2 + half;
                        MMA16816(acc[nt], qh[kb], kh[2 * half], kh[2 * half + 1]);
                        MMA16816(acc[nt], qh[kb], kl[2 * half], kl[2 * half + 1]);
                        MMA16816(acc[nt], ql[kb], kh[2 * half], kh[2 * half + 1]);
                    }
                }
            }

            const int row0 = qbase + wid * 16 + gq;
            const int row1 = row0 + 8;
            if (ktbase + 63 > qbase + wid * 16) {
#pragma unroll
                for (int nt = 0; nt < 8; nt++) {
#pragma unroll
                    for (int j = 0; j < 4; j++) {
                        const int col = ktbase + nt * 8 + c2 + (j & 1);
                        const int r   = (j < 2) ? row0 : row1;
                        float sv = acc[nt][j] * 0.125f;
                        if (col > r) sv = -1e30f;
                        acc[nt][j] = sv;
                    }
                }
            } else {
#pragma unroll
                for (int nt = 0; nt < 8; nt++)
#pragma unroll
                    for (int j = 0; j < 4; j++) acc[nt][j] *= 0.125f;
            }

            float mx0 = -1e30f, mx1 = -1e30f;
#pragma unroll
            for (int nt = 0; nt < 8; nt++) {
                mx0 = fmaxf(mx0, fmaxf(acc[nt][0], acc[nt][1]));
                mx1 = fmaxf(mx1, fmaxf(acc[nt][2], acc[nt][3]));
            }
            mx0 = fmaxf(mx0, __shfl_xor_sync(0xffffffffu, mx0, 1));
            mx0 = fmaxf(mx0, __shfl_xor_sync(0xffffffffu, mx0, 2));
            mx1 = fmaxf(mx1, __shfl_xor_sync(0xffffffffu, mx1, 1));
            mx1 = fmaxf(mx1, __shfl_xor_sync(0xffffffffu, mx1, 2));

            const float mn0 = fmaxf(m0, mx0), mn1 = fmaxf(m1, mx1);
            const float al0 = __expf(m0 - mn0), al1 = __expf(m1 - mn1);
            float s0 = 0.f, s1 = 0.f;
#pragma unroll
            for (int nt = 0; nt < 8; nt++) {
                float p0 = __expf(acc[nt][0] - mn0);
                float p1 = __expf(acc[nt][1] - mn0);
                float p2 = __expf(acc[nt][2] - mn1);
                float p3 = __expf(acc[nt][3] - mn1);
                acc[nt][0] = p0; acc[nt][1] = p1; acc[nt][2] = p2; acc[nt][3] = p3;
                s0 += p0 + p1;
                s1 += p2 + p3;
            }
            s0 += __shfl_xor_sync(0xffffffffu, s0, 1);
            s0 += __shfl_xor_sync(0xffffffffu, s0, 2);
            s1 += __shfl_xor_sync(0xffffffffu, s1, 1);
            s1 += __shfl_xor_sync(0xffffffffu, s1, 2);
            l0 = l0 * al0 + s0;
            l1 = l1 * al1 + s1;
            m0 = mn0; m1 = mn1;
#pragma unroll
            for (int nt = 0; nt < 8; nt++) {
                Oacc[nt][0] *= al0; Oacc[nt][1] *= al0;
                Oacc[nt][2] *= al1; Oacc[nt][3] *= al1;
            }

#pragma unroll
            for (int kb = 0; kb < 4; kb++) {
                uint32_t ph[4], pl[4];
                split2(acc[2 * kb][0],     acc[2 * kb][1],     ph[0], pl[0]);
                split2(acc[2 * kb][2],     acc[2 * kb][3],     ph[1], pl[1]);
                split2(acc[2 * kb + 1][0], acc[2 * kb + 1][1], ph[2], pl[2]);
                split2(acc[2 * kb + 1][2], acc[2 * kb + 1][3], ph[3], pl[3]);
                const int krow = kb * 16 + (lane & 7) + ((lane >> 3) & 1) * 8;
#pragma unroll
                for (int np = 0; np < 4; np++) {
                    const int ncol = np * 16 + ((lane >> 4) & 1) * 8;
                    uint32_t vh[4], vl[4];
                    const uint32_t ad = sb + 2 * APART + krow * AKSTRB + ncol * 2;
                    LDM_X4_T(vh, ad);
                    LDM_X4_T(vl, ad + APART);
#pragma unroll
                    for (int half = 0; half < 2; half++) {
                        const int nt = np * 2 + half;
                        MMA16816(Oacc[nt], ph, vh[2 * half], vh[2 * half + 1]);
                        MMA16816(Oacc[nt], ph, vl[2 * half], vl[2 * half + 1]);
                        MMA16816(Oacc[nt], pl, vh[2 * half], vh[2 * half + 1]);
                    }
                }
            }
        }
        __syncthreads();
    }

    // ---- epilogue: normalize, split to bf16 hi/lo, store into GEMM2 A-layout -
    const float inv0 = 1.0f / l0, inv1 = 1.0f / l1;
    const int r0 = qbase + wid * 16 + gq;            // token row in [0,SEQ)
    const size_t m0r = (size_t)b * SEQ + r0;         // row in [M, CDIM]
    const size_t m1r = m0r + 8;
    const int colb = h * HD + c2;
#pragma unroll
    for (int nt = 0; nt < 8; nt++) {
        uint32_t hi0, lo0, hi1, lo1;
        split2(Oacc[nt][0] * inv0, Oacc[nt][1] * inv0, hi0, lo0);
        split2(Oacc[nt][2] * inv1, Oacc[nt][3] * inv1, hi1, lo1);
        const size_t o0 = m0r * CDIM + colb + nt * 8;
        const size_t o1 = m1r * CDIM + colb + nt * 8;
        *reinterpret_cast<uint32_t*>(Yhi + o0) = hi0;
        *reinterpret_cast<uint32_t*>(Ylo + o0) = lo0;
        *reinterpret_cast<uint32_t*>(Yhi + o1) = hi1;
        *reinterpret_cast<uint32_t*>(Ylo + o1) = lo1;
    }
}

// ---------------- launch ----------------------------------------------------
extern "C" void kernel_launch(void* const* d_in, const int* in_sizes, int n_in,
                              void* d_out, int out_size)
{
    const float* x      = (const float*)d_in[0];
    const float* W_attn = (const float*)d_in[1];
    const float* b_attn = (const float*)d_in[2];
    const float* W_proj = (const float*)d_in[3];
    const float* b_proj = (const float*)d_in[4];
    float* out = (float*)d_out;

    float *qkv;
    __nv_bfloat16 *ahi, *alo, *w1hi, *w1lo, *w2hi, *w2lo;
    __nv_bfloat16 *qhi, *qlo, *khi, *klo, *vhi, *vlo;
    cudaGetSymbolAddress((void**)&qkv,  g_qkv);
    cudaGetSymbolAddress((void**)&ahi,  g_ahi);
    cudaGetSymbolAddress((void**)&alo,  g_alo);
    cudaGetSymbolAddress((void**)&w1hi, g_w1hi);
    cudaGetSymbolAddress((void**)&w1lo, g_w1lo);
    cudaGetSymbolAddress((void**)&w2hi, g_w2hi);
    cudaGetSymbolAddress((void**)&w2lo, g_w2lo);
    cudaGetSymbolAddress((void**)&qhi,  g_qhi);
    cudaGetSymbolAddress((void**)&qlo,  g_qlo);
    cudaGetSymbolAddress((void**)&khi,  g_khi);
    cudaGetSymbolAddress((void**)&klo,  g_klo);
    cudaGetSymbolAddress((void**)&vhi,  g_vhi);
    cudaGetSymbolAddress((void**)&vlo,  g_vlo);

    cudaFuncSetAttribute(gemm_mma_kernel,
                         cudaFuncAttributeMaxDynamicSharedMemorySize, GEMM_SMEM);
    cudaFuncSetAttribute(attn_mma_kernel,
                         cudaFuncAttributeMaxDynamicSharedMemorySize, ATTN_SMEM);

    // convert weights (transpose + split)
    {
        dim3 blk(32, 8);
        dim3 g1(C3 / 32, CDIM / 32);
        transpose_split_kernel<<<g1, blk>>>(CDIM, C3, W_attn, w1hi, w1lo);
        dim3 g2(CDIM / 32, CDIM / 32);
        transpose_split_kernel<<<g2, blk>>>(CDIM, CDIM, W_proj, w2hi, w2lo);
    }
    // convert x
    {
        int total4 = MROWS * CDIM / 4;
        convert_split_kernel<<<(total4 + 255) / 256, 256>>>(
            total4, (const float4*)x, (__nv_bfloat162*)ahi, (__nv_bfloat162*)alo);
    }
    // GEMM1: qkv = x @ W_attn + b_attn
    {
        dim3 grid(C3 / 128, MROWS / 128);
        gemm_mma_kernel<<<grid, 256, GEMM_SMEM>>>(CDIM, C3,
                                                  ahi, alo, w1hi, w1lo, b_attn, qkv);
    }
    // RoPE + scatter + split
    {
        int total = BATCH * SEQ * NHEAD * (HD / 2);
        rope_split_kernel<<<(total + 255) / 256, 256>>>(qkv, qhi, qlo, khi, klo, vhi, vlo);
    }
    // Flash attention (tensor cores), writes split-bf16 y directly
    {
        dim3 grid(SEQ / 128, NHEAD, BATCH);
        attn_mma_kernel<<<grid, 256, ATTN_SMEM>>>(qhi, qlo, khi, klo, vhi, vlo,
                                                  ahi, alo);
    }
    // GEMM2: out = y @ W_proj + b_proj
    {
        dim3 grid(CDIM / 128, MROWS / 128);
        gemm_mma_kernel<<<grid, 256, GEMM_SMEM>>>(CDIM, CDIM,
                                                  ahi, alo, w2hi, w2lo, b_proj, out);
    }
}